// round 12
// baseline (speedup 1.0000x reference)
#include <cuda_runtime.h>

#define N_NODES 50000
#define N_EDGES 600000
#define DIM 128
#define N_LAYERS 3
#define N_GRAPHS 512
#define BN_EPS 1e-5f
#define OUT_ELEMS (N_GRAPHS * N_LAYERS * DIM)

#define ROWS_PER_BLK 64
#define H1_STRIDE 132   // padded row stride for H1 tile (floats)

// Scratch (device globals; no allocation allowed)
__device__ float g_agg[N_NODES * DIM];            // aggregation output (mlp input)
__device__ float g_h2[N_NODES * DIM];             // raw mlp output (pre-BN)
__device__ float g_stats[N_LAYERS][2 * DIM];      // per-layer per-feature sum, sumsq
__device__ int   g_gcnt[N_GRAPHS];                // nodes per graph
// CSR build scratch
__device__ int g_deg[N_NODES];
__device__ int g_cur[N_NODES];
__device__ int g_off[N_NODES];
__device__ int g_esrc[N_EDGES];

// ---------------------------------------------------------------------------
// vector atomic add (sm_90+)
__device__ __forceinline__ void red_add_v4(float4* p, float4 v) {
    asm volatile("red.global.add.v4.f32 [%0], {%1, %2, %3, %4};\n"
                 :: "l"(p), "f"(v.x), "f"(v.y), "f"(v.z), "f"(v.w)
                 : "memory");
}

// packed f32x2 FMA (sm_100+; ptxas never auto-emits — PTX only)
__device__ __forceinline__ void fma2(unsigned long long& d,
                                     unsigned long long a, unsigned long long b) {
    asm("fma.rn.f32x2 %0, %1, %2, %0;" : "+l"(d) : "l"(a), "l"(b));
}
__device__ __forceinline__ unsigned long long pack2(float x) {
    unsigned long long r;
    asm("mov.b64 %0, {%1, %1};" : "=l"(r) : "f"(x));
    return r;
}
__device__ __forceinline__ float2 unpack2(unsigned long long v) {
    float2 f;
    asm("mov.b64 {%0, %1}, %2;" : "=f"(f.x), "=f"(f.y) : "l"(v));
    return f;
}

// ===========================================================================
// K_prep: zero deg/cur, graph counts, BN stats, and the output buffer
// ===========================================================================
__global__ void k_prep(float* __restrict__ out) {
    int i = blockIdx.x * blockDim.x + threadIdx.x;
    if (i < OUT_ELEMS) out[i] = 0.0f;
    if (i < N_NODES) { g_deg[i] = 0; g_cur[i] = 0; }
    if (i < N_GRAPHS) g_gcnt[i] = 0;
    if (i < N_LAYERS * 2 * DIM) ((float*)g_stats)[i] = 0.0f;
}

// ===========================================================================
// K_hist: degree histogram over dst; also per-graph node counts from batch
// ===========================================================================
__global__ void k_hist(const int* __restrict__ dst, const int* __restrict__ batch) {
    int e = blockIdx.x * blockDim.x + threadIdx.x;
    if (e < N_EDGES) atomicAdd(&g_deg[__ldg(dst + e)], 1);
    if (e < N_NODES) atomicAdd(&g_gcnt[__ldg(batch + e)], 1);
}

// ===========================================================================
// K_scan: single-block exclusive scan of g_deg -> g_off (1024 threads)
// ===========================================================================
#define SCAN_T 1024
#define SCAN_CH 49   // ceil(50000/1024)
__global__ __launch_bounds__(SCAN_T)
void k_scan() {
    __shared__ int s[SCAN_T];
    int t = threadIdx.x;
    int start = t * SCAN_CH;
    int end = min(start + SCAN_CH, N_NODES);
    int sum = 0;
    for (int i = start; i < end; i++) sum += g_deg[i];
    s[t] = sum;
    __syncthreads();
    #pragma unroll
    for (int d = 1; d < SCAN_T; d <<= 1) {
        int x = (t >= d) ? s[t - d] : 0;
        __syncthreads();
        s[t] += x;
        __syncthreads();
    }
    int run = (t > 0) ? s[t - 1] : 0;
    for (int i = start; i < end; i++) {
        g_off[i] = run;
        run += g_deg[i];
    }
}

// ===========================================================================
// K_place: bucket edges by dst
// ===========================================================================
__global__ void k_place(const int* __restrict__ src, const int* __restrict__ dst) {
    int e = blockIdx.x * blockDim.x + threadIdx.x;
    if (e >= N_EDGES) return;
    int d = __ldg(dst + e);
    int pos = g_off[d] + atomicAdd(&g_cur[d], 1);
    g_esrc[pos] = __ldg(src + e);
}

// ===========================================================================
// K_agg: agg[n] = BN_fold( h2raw[n] + sum h2raw[src] )
//   layer 0 (use_x): no BN fold, source is x.
//   layer >0: sc,sh from g_stats[prev]; agg = sc*sum + (deg+1)*sh.
//   warp per node, lane per float4. No atomics. 4-edge unroll for MLP.
// ===========================================================================
__global__ void k_agg(const float4* __restrict__ x, int use_x,
                      const float* __restrict__ gamma, const float* __restrict__ beta,
                      int prev_layer) {
    __shared__ float s_st[2 * DIM];
    if (!use_x && threadIdx.x < DIM) {
        int f = threadIdx.x;
        const float* st = g_stats[prev_layer];
        float n = (float)N_NODES;
        float mean = st[f] / n;
        float var = st[DIM + f] / n - mean * mean;
        var = fmaxf(var, 0.f);
        float sc = rsqrtf(var + BN_EPS) * __ldg(gamma + f);
        s_st[f] = sc;
        s_st[DIM + f] = fmaf(-mean, sc, __ldg(beta + f));
    }
    if (!use_x) __syncthreads();

    int gt = blockIdx.x * blockDim.x + threadIdx.x;
    int node = gt >> 5;
    int lane = gt & 31;
    if (node >= N_NODES) return;
    const float4* hin = use_x ? x : (const float4*)g_h2;

    float4 acc = __ldg(hin + node * 32 + lane);   // self term (eps=0)
    int deg = __ldg(g_deg + node);
    int e   = __ldg(g_off + node);
    int end = e + deg;

    for (; e + 3 < end; e += 4) {                 // MLP=4
        int s0 = __ldg(g_esrc + e);
        int s1 = __ldg(g_esrc + e + 1);
        int s2 = __ldg(g_esrc + e + 2);
        int s3 = __ldg(g_esrc + e + 3);
        float4 v0 = __ldg(hin + s0 * 32 + lane);
        float4 v1 = __ldg(hin + s1 * 32 + lane);
        float4 v2 = __ldg(hin + s2 * 32 + lane);
        float4 v3 = __ldg(hin + s3 * 32 + lane);
        acc.x += v0.x + v1.x + v2.x + v3.x;
        acc.y += v0.y + v1.y + v2.y + v3.y;
        acc.z += v0.z + v1.z + v2.z + v3.z;
        acc.w += v0.w + v1.w + v2.w + v3.w;
    }
    for (; e < end; e++) {
        int s0 = __ldg(g_esrc + e);
        float4 v0 = __ldg(hin + s0 * 32 + lane);
        acc.x += v0.x; acc.y += v0.y; acc.z += v0.z; acc.w += v0.w;
    }

    if (!use_x) {
        float4 s = ((const float4*)s_st)[lane];
        float4 t = ((const float4*)s_st)[32 + lane];
        float k1 = (float)(deg + 1);
        acc.x = fmaf(acc.x, s.x, k1 * t.x);
        acc.y = fmaf(acc.y, s.y, k1 * t.y);
        acc.z = fmaf(acc.z, s.z, k1 * t.z);
        acc.w = fmaf(acc.w, s.w, k1 * t.w);
    }
    ((float4*)g_agg)[node * 32 + lane] = acc;
}

// ===========================================================================
// K_mlp: h2raw = relu(relu(agg@W1+b1)@W2+b2) -> g_h2,
//   BN stats (sum,sumsq) -> g_stats[layer], raw graph pool -> out (red.v4)
// ===========================================================================
__global__ __launch_bounds__(256, 1)
void k_mlp(const float4* __restrict__ W1, const float* __restrict__ b1,
           const float4* __restrict__ W2, const float* __restrict__ b2,
           const int* __restrict__ batch, float* __restrict__ out, int layer) {
    extern __shared__ float sm[];
    float*  As  = sm;                        // [64][128]
    float*  Ws  = sm + ROWS_PER_BLK * DIM;   // [128][128]
    float*  H1  = Ws + DIM * DIM;            // [64][132]
    float4* As4 = (float4*)As;
    float4* Ws4 = (float4*)Ws;
    const ulonglong2* Wp = (const ulonglong2*)Ws;

    const int tid  = threadIdx.x;
    const int base = blockIdx.x * ROWS_PER_BLK;

    #pragma unroll
    for (int i = 0; i < 16; i++) Ws4[tid + i * 256] = W1[tid + i * 256];
    const float4* A4 = (const float4*)g_agg;
    #pragma unroll
    for (int i = 0; i < 8; i++) {
        int idx = tid + i * 256;
        int r = idx >> 5, kq = idx & 31;
        float4 v = make_float4(0.f, 0.f, 0.f, 0.f);
        if (base + r < N_NODES) v = A4[(base + r) * 32 + kq];
        As4[idx] = v;
    }
    __syncthreads();

    const int colg = tid & 15;
    const int rowg = tid >> 4;
    const int c0 = colg * 8, r0 = rowg * 4;

    // ---- GEMM 1: acc = A @ W1  (f32x2) ----
    unsigned long long acc[4][4];
    #pragma unroll
    for (int i = 0; i < 4; i++)
        #pragma unroll
        for (int p = 0; p < 4; p++) acc[i][p] = 0ull;

    #pragma unroll 4
    for (int k = 0; k < DIM; k++) {
        unsigned long long a0 = pack2(As[(r0 + 0) * DIM + k]);
        unsigned long long a1 = pack2(As[(r0 + 1) * DIM + k]);
        unsigned long long a2 = pack2(As[(r0 + 2) * DIM + k]);
        unsigned long long a3 = pack2(As[(r0 + 3) * DIM + k]);
        ulonglong2 q0 = Wp[k * 32 + colg * 2];
        ulonglong2 q1 = Wp[k * 32 + colg * 2 + 1];
        fma2(acc[0][0], a0, q0.x); fma2(acc[0][1], a0, q0.y);
        fma2(acc[0][2], a0, q1.x); fma2(acc[0][3], a0, q1.y);
        fma2(acc[1][0], a1, q0.x); fma2(acc[1][1], a1, q0.y);
        fma2(acc[1][2], a1, q1.x); fma2(acc[1][3], a1, q1.y);
        fma2(acc[2][0], a2, q0.x); fma2(acc[2][1], a2, q0.y);
        fma2(acc[2][2], a2, q1.x); fma2(acc[2][3], a2, q1.y);
        fma2(acc[3][0], a3, q0.x); fma2(acc[3][1], a3, q0.y);
        fma2(acc[3][2], a3, q1.x); fma2(acc[3][3], a3, q1.y);
    }

    #pragma unroll
    for (int p = 0; p < 4; p++) {
        float b_lo = __ldg(b1 + c0 + 2 * p);
        float b_hi = __ldg(b1 + c0 + 2 * p + 1);
        #pragma unroll
        for (int i = 0; i < 4; i++) {
            float2 f = unpack2(acc[i][p]);
            H1[(r0 + i) * H1_STRIDE + c0 + 2 * p]     = fmaxf(f.x + b_lo, 0.f);
            H1[(r0 + i) * H1_STRIDE + c0 + 2 * p + 1] = fmaxf(f.y + b_hi, 0.f);
        }
    }
    __syncthreads();

    #pragma unroll
    for (int i = 0; i < 16; i++) Ws4[tid + i * 256] = W2[tid + i * 256];
    if (tid < DIM) { As[tid] = 0.f; As[DIM + tid] = 0.f; }
    __syncthreads();

    // ---- GEMM 2: acc = H1 @ W2 ----
    #pragma unroll
    for (int i = 0; i < 4; i++)
        #pragma unroll
        for (int p = 0; p < 4; p++) acc[i][p] = 0ull;

    #pragma unroll 4
    for (int k = 0; k < DIM; k++) {
        unsigned long long a0 = pack2(H1[(r0 + 0) * H1_STRIDE + k]);
        unsigned long long a1 = pack2(H1[(r0 + 1) * H1_STRIDE + k]);
        unsigned long long a2 = pack2(H1[(r0 + 2) * H1_STRIDE + k]);
        unsigned long long a3 = pack2(H1[(r0 + 3) * H1_STRIDE + k]);
        ulonglong2 q0 = Wp[k * 32 + colg * 2];
        ulonglong2 q1 = Wp[k * 32 + colg * 2 + 1];
        fma2(acc[0][0], a0, q0.x); fma2(acc[0][1], a0, q0.y);
        fma2(acc[0][2], a0, q1.x); fma2(acc[0][3], a0, q1.y);
        fma2(acc[1][0], a1, q0.x); fma2(acc[1][1], a1, q0.y);
        fma2(acc[1][2], a1, q1.x); fma2(acc[1][3], a1, q1.y);
        fma2(acc[2][0], a2, q0.x); fma2(acc[2][1], a2, q0.y);
        fma2(acc[2][2], a2, q1.x); fma2(acc[2][3], a2, q1.y);
        fma2(acc[3][0], a3, q0.x); fma2(acc[3][1], a3, q0.y);
        fma2(acc[3][2], a3, q1.x); fma2(acc[3][3], a3, q1.y);
    }

    float v[4][8];
    #pragma unroll
    for (int p = 0; p < 4; p++) {
        float b_lo = __ldg(b2 + c0 + 2 * p);
        float b_hi = __ldg(b2 + c0 + 2 * p + 1);
        #pragma unroll
        for (int i = 0; i < 4; i++) {
            float2 f = unpack2(acc[i][p]);
            v[i][2 * p]     = fmaxf(f.x + b_lo, 0.f);
            v[i][2 * p + 1] = fmaxf(f.y + b_hi, 0.f);
        }
    }

    // store raw h2; pool raw h2 into out (per-graph red)
    float4* O4 = (float4*)g_h2;
    #pragma unroll
    for (int i = 0; i < 4; i++) {
        int row = base + r0 + i;
        if (row < N_NODES) {
            float4 lo = make_float4(v[i][0], v[i][1], v[i][2], v[i][3]);
            float4 hi = make_float4(v[i][4], v[i][5], v[i][6], v[i][7]);
            O4[row * 32 + colg * 2]     = lo;
            O4[row * 32 + colg * 2 + 1] = hi;
            int g = __ldg(batch + row);
            float* ob = out + g * (N_LAYERS * DIM) + layer * DIM + c0;
            red_add_v4((float4*)ob, lo);
            red_add_v4((float4*)(ob + 4), hi);
        }
    }

    // BN stats
    #pragma unroll
    for (int j = 0; j < 8; j++) {
        float s = 0.f, q = 0.f;
        #pragma unroll
        for (int i = 0; i < 4; i++) {
            if (base + r0 + i < N_NODES) { s += v[i][j]; q += v[i][j] * v[i][j]; }
        }
        atomicAdd(&As[c0 + j], s);
        atomicAdd(&As[DIM + c0 + j], q);
    }
    __syncthreads();
    if (tid < DIM) {
        atomicAdd(&g_stats[layer][tid], As[tid]);
        atomicAdd(&g_stats[layer][DIM + tid], As[DIM + tid]);
    }
}

// ===========================================================================
// K_poolfix: out[g, layer*DIM+f] = sc[f]*raw + cnt[g]*sh[f]   (in place)
// ===========================================================================
__global__ void k_poolfix(float* __restrict__ out,
                          const float* __restrict__ gamma, const float* __restrict__ beta,
                          int layer) {
    int idx = blockIdx.x * blockDim.x + threadIdx.x;  // 65536 exact
    int g = idx >> 7, f = idx & 127;
    const float* st = g_stats[layer];
    float n = (float)N_NODES;
    float mean = st[f] / n;
    float var = st[DIM + f] / n - mean * mean;
    var = fmaxf(var, 0.f);
    float sc = rsqrtf(var + BN_EPS) * __ldg(gamma + f);
    float sh = fmaf(-mean, sc, __ldg(beta + f));
    float* p = out + g * (N_LAYERS * DIM) + layer * DIM + f;
    *p = fmaf(*p, sc, (float)__ldg(g_gcnt + g) * sh);
}

// ---------------------------------------------------------------------------
extern "C" void kernel_launch(void* const* d_in, const int* in_sizes, int n_in,
                              void* d_out, int out_size) {
    const float* x      = (const float*)d_in[0];
    const int*   ei     = (const int*)d_in[1];
    const int*   batch  = (const int*)d_in[2];
    const float* W1s    = (const float*)d_in[3];
    const float* b1s    = (const float*)d_in[4];
    const float* W2s    = (const float*)d_in[5];
    const float* b2s    = (const float*)d_in[6];
    const float* gammas = (const float*)d_in[7];
    const float* betas  = (const float*)d_in[8];
    float* out = (float*)d_out;

    const int smem_mlp = (ROWS_PER_BLK * DIM + DIM * DIM + ROWS_PER_BLK * H1_STRIDE) * 4;
    cudaFuncSetAttribute(k_mlp, cudaFuncAttributeMaxDynamicSharedMemorySize, smem_mlp);

    const int* src = ei;
    const int* dst = ei + N_EDGES;

    const int node_blocks = (N_NODES * 32) / 256;                          // 6250
    const int edge_blocks = (N_EDGES + 255) / 256;                         // 2344
    const int prep_blocks = (OUT_ELEMS + 255) / 256;                       // 768
    const int mlp_blocks  = (N_NODES + ROWS_PER_BLK - 1) / ROWS_PER_BLK;   // 782
    const int pool_blocks = (N_GRAPHS * DIM) / 256;                        // 256

    // --- prep + CSR build (edges shared by all layers) ---
    k_prep<<<prep_blocks, 256>>>(out);
    k_hist<<<edge_blocks, 256>>>(dst, batch);
    k_scan<<<1, SCAN_T>>>();
    k_place<<<edge_blocks, 256>>>(src, dst);

    for (int l = 0; l < N_LAYERS; l++) {
        int use_x = (l == 0) ? 1 : 0;
        k_agg<<<node_blocks, 256>>>((const float4*)x, use_x,
                                    gammas + (l - 1) * DIM, betas + (l - 1) * DIM,
                                    l - 1);
        k_mlp<<<mlp_blocks, 256, smem_mlp>>>(
            (const float4*)(W1s + l * DIM * DIM), b1s + l * DIM,
            (const float4*)(W2s + l * DIM * DIM), b2s + l * DIM,
            batch, out, l);
        k_poolfix<<<pool_blocks, 256>>>(out, gammas + l * DIM, betas + l * DIM, l);
    }
}

// round 13
// speedup vs baseline: 1.4078x; 1.4078x over previous
#include <cuda_runtime.h>

#define N_NODES 50000
#define N_EDGES 600000
#define DIM 128
#define N_LAYERS 3
#define N_GRAPHS 512
#define BN_EPS 1e-5f
#define OUT_ELEMS (N_GRAPHS * N_LAYERS * DIM)

#define MROWS 128        // rows per mlp block
#define AST 130          // As / H1 smem row stride (floats): 8*130 % 32 = 16 -> conflict-free

// Scratch (device globals; no allocation allowed)
__device__ float g_agg[N_NODES * DIM];    // agg / h2 buffer (in-place reuse)
__device__ float g_h[N_NODES * DIM];      // h after BN
__device__ float g_stats[2 * DIM];        // per-feature sum, sumsq
// CSR build scratch
__device__ int g_deg[N_NODES];
__device__ int g_cur[N_NODES];
__device__ int g_off[N_NODES];
__device__ int g_esrc[N_EDGES];

// ---------------------------------------------------------------------------
__device__ __forceinline__ void red_add_v4(float4* p, float4 v) {
    asm volatile("red.global.add.v4.f32 [%0], {%1, %2, %3, %4};\n"
                 :: "l"(p), "f"(v.x), "f"(v.y), "f"(v.z), "f"(v.w)
                 : "memory");
}
__device__ __forceinline__ void fma2(unsigned long long& d,
                                     unsigned long long a, unsigned long long b) {
    asm("fma.rn.f32x2 %0, %1, %2, %0;" : "+l"(d) : "l"(a), "l"(b));
}
__device__ __forceinline__ unsigned long long pack2(float x) {
    unsigned long long r;
    asm("mov.b64 %0, {%1, %1};" : "=l"(r) : "f"(x));
    return r;
}
__device__ __forceinline__ float2 unpack2(unsigned long long v) {
    float2 f;
    asm("mov.b64 {%0, %1}, %2;" : "=f"(f.x), "=f"(f.y) : "l"(v));
    return f;
}

// ===========================================================================
// K_prep: zero deg/cur and the output buffer
// ===========================================================================
__global__ void k_prep(float* __restrict__ out) {
    int i = blockIdx.x * blockDim.x + threadIdx.x;
    if (i < OUT_ELEMS) out[i] = 0.0f;
    if (i < N_NODES) { g_deg[i] = 0; g_cur[i] = 0; }
}

__global__ void k_hist(const int* __restrict__ dst) {
    int e = blockIdx.x * blockDim.x + threadIdx.x;
    if (e < N_EDGES) atomicAdd(&g_deg[__ldg(dst + e)], 1);
}

// single-block exclusive scan of g_deg -> g_off
#define SCAN_T 1024
#define SCAN_CH 49
__global__ __launch_bounds__(SCAN_T)
void k_scan() {
    __shared__ int s[SCAN_T];
    int t = threadIdx.x;
    int start = t * SCAN_CH;
    int end = min(start + SCAN_CH, N_NODES);
    int sum = 0;
    for (int i = start; i < end; i++) sum += g_deg[i];
    s[t] = sum;
    __syncthreads();
    #pragma unroll
    for (int d = 1; d < SCAN_T; d <<= 1) {
        int x = (t >= d) ? s[t - d] : 0;
        __syncthreads();
        s[t] += x;
        __syncthreads();
    }
    int run = (t > 0) ? s[t - 1] : 0;
    for (int i = start; i < end; i++) {
        g_off[i] = run;
        run += g_deg[i];
    }
}

__global__ void k_place(const int* __restrict__ src, const int* __restrict__ dst) {
    int e = blockIdx.x * blockDim.x + threadIdx.x;
    if (e >= N_EDGES) return;
    int d = __ldg(dst + e);
    int pos = g_off[d] + atomicAdd(&g_cur[d], 1);
    g_esrc[pos] = __ldg(src + e);
}

// ===========================================================================
// K_agg: agg[n] = h_in[n] + sum h_in[src]; warp/node, lane/float4, 4-unroll.
//        Block 0 zeroes g_stats for the upcoming k_mlp.
// ===========================================================================
__global__ void k_agg(const float4* __restrict__ x, int use_x) {
    if (blockIdx.x == 0 && threadIdx.x < 2 * DIM) g_stats[threadIdx.x] = 0.0f;
    int gt = blockIdx.x * blockDim.x + threadIdx.x;
    int node = gt >> 5;
    int lane = gt & 31;
    if (node >= N_NODES) return;
    const float4* hin = use_x ? x : (const float4*)g_h;

    float4 acc = __ldg(hin + node * 32 + lane);   // self term (eps=0)
    int e   = __ldg(g_off + node);
    int end = e + __ldg(g_deg + node);

    for (; e + 3 < end; e += 4) {
        int s0 = __ldg(g_esrc + e);
        int s1 = __ldg(g_esrc + e + 1);
        int s2 = __ldg(g_esrc + e + 2);
        int s3 = __ldg(g_esrc + e + 3);
        float4 v0 = __ldg(hin + s0 * 32 + lane);
        float4 v1 = __ldg(hin + s1 * 32 + lane);
        float4 v2 = __ldg(hin + s2 * 32 + lane);
        float4 v3 = __ldg(hin + s3 * 32 + lane);
        acc.x += v0.x + v1.x + v2.x + v3.x;
        acc.y += v0.y + v1.y + v2.y + v3.y;
        acc.z += v0.z + v1.z + v2.z + v3.z;
        acc.w += v0.w + v1.w + v2.w + v3.w;
    }
    for (; e < end; e++) {
        int s0 = __ldg(g_esrc + e);
        float4 v0 = __ldg(hin + s0 * 32 + lane);
        acc.x += v0.x; acc.y += v0.y; acc.z += v0.z; acc.w += v0.w;
    }
    ((float4*)g_agg)[node * 32 + lane] = acc;
}

// ===========================================================================
// K_mlp: 128-row block, 8x8 thread tile, 256 threads, f32x2 FMA.
//   h2 = relu(relu(agg@W1+b1)@W2+b2) in-place on g_agg + BN stats.
//   Thread owns cols {4*colg..+3} and {64+4*colg..+3}, rows {8*rowg..+7}.
// ===========================================================================
__global__ __launch_bounds__(256, 1)
void k_mlp(const float4* __restrict__ W1, const float* __restrict__ b1,
           const float4* __restrict__ W2, const float* __restrict__ b2) {
    extern __shared__ float sm[];
    float*  As = sm;                      // [128][AST]
    float*  Ws = sm + MROWS * AST;        // [128][128] k-major
    float*  H1 = Ws + DIM * DIM;          // [128][AST]
    float4* Ws4 = (float4*)Ws;

    const int tid  = threadIdx.x;
    const int base = blockIdx.x * MROWS;

    // load W1 (4096 float4)
    #pragma unroll
    for (int i = 0; i < 16; i++) Ws4[tid + i * 256] = W1[tid + i * 256];
    // load A tile with row stride AST (float2 stores keep 8B alignment)
    const float4* A4 = (const float4*)g_agg;
    #pragma unroll
    for (int i = 0; i < 16; i++) {
        int idx = tid + i * 256;
        int r = idx >> 5, kq = idx & 31;
        float4 v = make_float4(0.f, 0.f, 0.f, 0.f);
        if (base + r < N_NODES) v = A4[(base + r) * 32 + kq];
        float2* p2 = (float2*)(As + r * AST + kq * 4);
        p2[0] = make_float2(v.x, v.y);
        p2[1] = make_float2(v.z, v.w);
    }
    __syncthreads();

    const int colg = tid & 15;
    const int rowg = tid >> 4;
    const int r0 = rowg * 8;
    const int cb0 = colg * 4;          // first col group
    const int cb1 = 64 + colg * 4;     // second col group

    // ---- GEMM 1: acc = A @ W1 ----
    unsigned long long acc[8][4];
    #pragma unroll
    for (int i = 0; i < 8; i++)
        #pragma unroll
        for (int p = 0; p < 4; p++) acc[i][p] = 0ull;

    #pragma unroll 2
    for (int k = 0; k < DIM; k++) {
        unsigned long long a[8];
        #pragma unroll
        for (int i = 0; i < 8; i++) a[i] = pack2(As[(r0 + i) * AST + k]);
        ulonglong2 q0 = *(const ulonglong2*)(Ws + k * DIM + cb0);
        ulonglong2 q1 = *(const ulonglong2*)(Ws + k * DIM + cb1);
        #pragma unroll
        for (int i = 0; i < 8; i++) {
            fma2(acc[i][0], a[i], q0.x);
            fma2(acc[i][1], a[i], q0.y);
            fma2(acc[i][2], a[i], q1.x);
            fma2(acc[i][3], a[i], q1.y);
        }
    }

    // epilogue 1: relu(+b1) -> H1 (row-major, stride AST)
    #pragma unroll
    for (int p = 0; p < 4; p++) {
        int colp = (p < 2) ? (cb0 + 2 * p) : (cb1 + 2 * (p - 2));
        float b_lo = __ldg(b1 + colp);
        float b_hi = __ldg(b1 + colp + 1);
        #pragma unroll
        for (int i = 0; i < 8; i++) {
            float2 f = unpack2(acc[i][p]);
            H1[(r0 + i) * AST + colp]     = fmaxf(f.x + b_lo, 0.f);
            H1[(r0 + i) * AST + colp + 1] = fmaxf(f.y + b_hi, 0.f);
        }
    }
    __syncthreads();

    // load W2 over Ws; zero smem stat buffer (As region now idle)
    #pragma unroll
    for (int i = 0; i < 16; i++) Ws4[tid + i * 256] = W2[tid + i * 256];
    As[tid] = 0.f;   // 256 slots: [0..127]=sum, [128..255]=sumsq
    __syncthreads();

    // ---- GEMM 2: acc = H1 @ W2 ----
    #pragma unroll
    for (int i = 0; i < 8; i++)
        #pragma unroll
        for (int p = 0; p < 4; p++) acc[i][p] = 0ull;

    #pragma unroll 2
    for (int k = 0; k < DIM; k++) {
        unsigned long long a[8];
        #pragma unroll
        for (int i = 0; i < 8; i++) a[i] = pack2(H1[(r0 + i) * AST + k]);
        ulonglong2 q0 = *(const ulonglong2*)(Ws + k * DIM + cb0);
        ulonglong2 q1 = *(const ulonglong2*)(Ws + k * DIM + cb1);
        #pragma unroll
        for (int i = 0; i < 8; i++) {
            fma2(acc[i][0], a[i], q0.x);
            fma2(acc[i][1], a[i], q0.y);
            fma2(acc[i][2], a[i], q1.x);
            fma2(acc[i][3], a[i], q1.y);
        }
    }

    // epilogue 2: relu(+b2) -> v, store h2 (float4 per col group), BN stats
    float v[8][8];   // [row][jj]: jj 0..3 -> cols cb0..cb0+3, jj 4..7 -> cb1..cb1+3
    #pragma unroll
    for (int p = 0; p < 4; p++) {
        int colp = (p < 2) ? (cb0 + 2 * p) : (cb1 + 2 * (p - 2));
        int jj = 2 * p;
        float b_lo = __ldg(b2 + colp);
        float b_hi = __ldg(b2 + colp + 1);
        #pragma unroll
        for (int i = 0; i < 8; i++) {
            float2 f = unpack2(acc[i][p]);
            v[i][jj]     = fmaxf(f.x + b_lo, 0.f);
            v[i][jj + 1] = fmaxf(f.y + b_hi, 0.f);
        }
    }

    float4* O4 = (float4*)g_agg;
    #pragma unroll
    for (int i = 0; i < 8; i++) {
        int row = base + r0 + i;
        if (row < N_NODES) {
            O4[row * 32 + colg]      = make_float4(v[i][0], v[i][1], v[i][2], v[i][3]);
            O4[row * 32 + 16 + colg] = make_float4(v[i][4], v[i][5], v[i][6], v[i][7]);
        }
    }

    #pragma unroll
    for (int jj = 0; jj < 8; jj++) {
        int col = (jj < 4) ? (cb0 + jj) : (cb1 + jj - 4);
        float s = 0.f, q = 0.f;
        #pragma unroll
        for (int i = 0; i < 8; i++) {
            if (base + r0 + i < N_NODES) { s += v[i][jj]; q += v[i][jj] * v[i][jj]; }
        }
        atomicAdd(&As[col], s);
        atomicAdd(&As[DIM + col], q);
    }
    __syncthreads();
    atomicAdd(&g_stats[tid], As[tid]);   // all 256 threads, one slot each
}

// ===========================================================================
// K_apply: BN -> g_h, pool into out (scale/shift computed per block)
// ===========================================================================
__global__ void k_apply(const int* __restrict__ batch, float* __restrict__ out,
                        const float* __restrict__ gamma, const float* __restrict__ beta,
                        int layer) {
    __shared__ float s_st[2 * DIM];
    if (threadIdx.x < DIM) {
        int f = threadIdx.x;
        float n = (float)N_NODES;
        float mean = g_stats[f] / n;
        float var = g_stats[DIM + f] / n - mean * mean;
        var = fmaxf(var, 0.f);
        float sc = rsqrtf(var + BN_EPS) * __ldg(gamma + f);
        s_st[f] = sc;
        s_st[DIM + f] = fmaf(-mean, sc, __ldg(beta + f));
    }
    __syncthreads();

    int idx = blockIdx.x * blockDim.x + threadIdx.x;  // 1.6M exact
    int row = idx >> 5, cq = idx & 31;
    float4 xv = ((const float4*)g_agg)[idx];
    float4 s = ((const float4*)s_st)[cq];
    float4 t = ((const float4*)s_st)[32 + cq];
    float4 y;
    y.x = fmaf(xv.x, s.x, t.x);
    y.y = fmaf(xv.y, s.y, t.y);
    y.z = fmaf(xv.z, s.z, t.z);
    y.w = fmaf(xv.w, s.w, t.w);
    ((float4*)g_h)[idx] = y;
    int g = __ldg(batch + row);
    red_add_v4((float4*)(out + g * (N_LAYERS * DIM) + layer * DIM + (cq << 2)), y);
}

// ---------------------------------------------------------------------------
extern "C" void kernel_launch(void* const* d_in, const int* in_sizes, int n_in,
                              void* d_out, int out_size) {
    const float* x      = (const float*)d_in[0];
    const int*   ei     = (const int*)d_in[1];
    const int*   batch  = (const int*)d_in[2];
    const float* W1s    = (const float*)d_in[3];
    const float* b1s    = (const float*)d_in[4];
    const float* W2s    = (const float*)d_in[5];
    const float* b2s    = (const float*)d_in[6];
    const float* gammas = (const float*)d_in[7];
    const float* betas  = (const float*)d_in[8];
    float* out = (float*)d_out;

    const int smem_mlp = (MROWS * AST + DIM * DIM + MROWS * AST) * 4;  // 198656 B
    cudaFuncSetAttribute(k_mlp, cudaFuncAttributeMaxDynamicSharedMemorySize, smem_mlp);

    const int* src = ei;
    const int* dst = ei + N_EDGES;

    const int node_blocks = (N_NODES * 32) / 256;                 // 6250
    const int edge_blocks = (N_EDGES + 255) / 256;                // 2344
    const int prep_blocks = (OUT_ELEMS + 255) / 256;              // 768
    const int mlp_blocks  = (N_NODES + MROWS - 1) / MROWS;        // 391

    k_prep<<<prep_blocks, 256>>>(out);
    k_hist<<<edge_blocks, 256>>>(dst);
    k_scan<<<1, SCAN_T>>>();
    k_place<<<edge_blocks, 256>>>(src, dst);

    for (int l = 0; l < N_LAYERS; l++) {
        int use_x = (l == 0) ? 1 : 0;
        k_agg<<<node_blocks, 256>>>((const float4*)x, use_x);
        k_mlp<<<mlp_blocks, 256, smem_mlp>>>(
            (const float4*)(W1s + l * DIM * DIM), b1s + l * DIM,
            (const float4*)(W2s + l * DIM * DIM), b2s + l * DIM);
        k_apply<<<node_blocks, 256>>>(batch, out, gammas + l * DIM, betas + l * DIM, l);
    }
}